// round 8
// baseline (speedup 1.0000x reference)
#include <cuda_runtime.h>
#include <cstdint>

// FM second-order term via mma.sync (HMMA) split-bf16 GEMM.
//   sum_emb = features @ W  (M=16384, K=200->208, N=64), 3 bf16 products
//   out[b]  = sum_e sum_emb[b,e]^2 - sum_f features[b,f]^2 * w2sum[f]
// R8: prep kernel pre-converts W -> swizzled bf16 hi/lo blocks + w2sum in
// device globals. Main: MTILE=64, 256 thr, 2 CTAs/SM for phase overlap;
// B arrives via cp.async burst; A staged fp32->bf16 hi/lo in registers.
// 8 warps = 2 kg x 2 mg x 2 ng, warp tile 32x32 over half of K.

typedef unsigned long long ull;

constexpr int F_DIM = 200;
constexpr int E_DIM = 64;
constexpr int MTILE = 64;
constexpr int THREADS = 256;

constexpr int SA_B = 432;               // A row stride bytes (216 bf16)
constexpr int CP_S = 68;                // partial-C row stride (floats)

constexpr int SM_A_HI = 0;              // 64*432 = 27648
constexpr int SM_A_LO = 27648;
constexpr int SM_B_HI = 55296;          // 13 blocks * 2048 = 26624
constexpr int SM_B_LO = 81920;
constexpr int SM_SQS  = 108544;         // 64*4
constexpr int SM_PART = 108800;         // 2*64*4
constexpr int SMEM_TOTAL = 109312;
constexpr int SM_CP = 0;                // partial C aliases A_HI (17408<=27648)

// prep outputs: B in swizzled block layout (block s = 16 k-rows * 128B;
// row r, 16B chunk c at r*128 + ((c ^ (r&7))<<4)), plus w2sum.
__device__ __align__(16) unsigned char gBhi[26624];
__device__ __align__(16) unsigned char gBlo[26624];
__device__ __align__(16) float gW2s[200];

__device__ __forceinline__ uint32_t smem_u32(const void* p) {
    return (uint32_t)__cvta_generic_to_shared(p);
}
__device__ __forceinline__ uint32_t cvt_bf16x2(float lo, float hi) {
    uint32_t r;
    asm("cvt.rn.bf16x2.f32 %0, %1, %2;" : "=r"(r) : "f"(hi), "f"(lo));
    return r;
}
__device__ __forceinline__ void split_bf16(float2 x, uint32_t& hi, uint32_t& lo) {
    hi = cvt_bf16x2(x.x, x.y);
    float h0 = __uint_as_float(hi << 16);
    float h1 = __uint_as_float(hi & 0xFFFF0000u);
    lo = cvt_bf16x2(x.x - h0, x.y - h1);
}
__device__ __forceinline__ void cp_async16(uint32_t s, const void* g) {
    asm volatile("cp.async.cg.shared.global [%0], [%1], 16;" :: "r"(s), "l"(g));
}
__device__ __forceinline__ void ldm_x4(uint32_t* r, uint32_t a) {
    asm volatile("ldmatrix.sync.aligned.m8n8.x4.shared.b16 {%0,%1,%2,%3}, [%4];"
                 : "=r"(r[0]), "=r"(r[1]), "=r"(r[2]), "=r"(r[3]) : "r"(a));
}
__device__ __forceinline__ void ldm_x4_t(uint32_t* r, uint32_t a) {
    asm volatile("ldmatrix.sync.aligned.m8n8.x4.trans.shared.b16 {%0,%1,%2,%3}, [%4];"
                 : "=r"(r[0]), "=r"(r[1]), "=r"(r[2]), "=r"(r[3]) : "r"(a));
}
__device__ __forceinline__ void mma_bf16(float* c, const uint32_t* a,
                                         uint32_t b0, uint32_t b1) {
    asm volatile(
        "mma.sync.aligned.m16n8k16.row.col.f32.bf16.bf16.f32 "
        "{%0,%1,%2,%3}, {%4,%5,%6,%7}, {%8,%9}, {%0,%1,%2,%3};"
        : "+f"(c[0]), "+f"(c[1]), "+f"(c[2]), "+f"(c[3])
        : "r"(a[0]), "r"(a[1]), "r"(a[2]), "r"(a[3]), "r"(b0), "r"(b1));
}

// ---------------- prep: convert W once, compute w2sum ----------------
__global__ void __launch_bounds__(256)
prep_kernel(const float* __restrict__ W)
{
    const int tid = threadIdx.x;
    const int k = blockIdx.x * 8 + (tid >> 5);   // B row 0..207
    const int j = tid & 31;                      // float2 pair within row
    uint32_t hi = 0, lo = 0;
    float2 x = make_float2(0.f, 0.f);
    if (k < F_DIM) {
        x = *(const float2*)(W + (size_t)k * E_DIM + 2 * j);
        split_bf16(x, hi, lo);
    }
    const int s = k >> 4, r = k & 15;
    const uint32_t off = (uint32_t)(s * 2048 + r * 128 +
                         (((j >> 2) ^ (r & 7)) << 4) + (j & 3) * 4);
    *(uint32_t*)(gBhi + off) = hi;
    *(uint32_t*)(gBlo + off) = lo;

    float s2 = fmaf(x.x, x.x, x.y * x.y);
    s2 += __shfl_xor_sync(0xffffffffu, s2, 1);
    s2 += __shfl_xor_sync(0xffffffffu, s2, 2);
    s2 += __shfl_xor_sync(0xffffffffu, s2, 4);
    s2 += __shfl_xor_sync(0xffffffffu, s2, 8);
    s2 += __shfl_xor_sync(0xffffffffu, s2, 16);
    if (j == 0 && k < F_DIM) gW2s[k] = s2;
}

// one k-step: 8 ldmatrix + 24 HMMA (hh*8, hl*8, lh*8 - chain-free order)
__device__ __forceinline__ void kstep(
    int k, uint32_t aHi, uint32_t aLo, uint32_t bHi, uint32_t bLo,
    float c[2][4][4])
{
    const uint32_t ka = (uint32_t)(k * 32);
    const uint32_t kb = (uint32_t)(k * 2048);
    uint32_t ah[2][4], al[2][4], bh[2][4], bl[2][4];
    ldm_x4(ah[0], aHi + ka);
    ldm_x4(ah[1], aHi + ka + 16 * SA_B);
    ldm_x4(al[0], aLo + ka);
    ldm_x4(al[1], aLo + ka + 16 * SA_B);
    ldm_x4_t(bh[0], (bHi + kb));
    ldm_x4_t(bh[1], (bHi + kb) ^ 32u);
    ldm_x4_t(bl[0], (bLo + kb));
    ldm_x4_t(bl[1], (bLo + kb) ^ 32u);
    #pragma unroll
    for (int jp = 0; jp < 2; ++jp)
        #pragma unroll
        for (int mi = 0; mi < 2; ++mi) {
            mma_bf16(c[mi][2 * jp],     ah[mi], bh[jp][0], bh[jp][1]);
            mma_bf16(c[mi][2 * jp + 1], ah[mi], bh[jp][2], bh[jp][3]);
        }
    #pragma unroll
    for (int jp = 0; jp < 2; ++jp)
        #pragma unroll
        for (int mi = 0; mi < 2; ++mi) {
            mma_bf16(c[mi][2 * jp],     ah[mi], bl[jp][0], bl[jp][1]);
            mma_bf16(c[mi][2 * jp + 1], ah[mi], bl[jp][2], bl[jp][3]);
        }
    #pragma unroll
    for (int jp = 0; jp < 2; ++jp)
        #pragma unroll
        for (int mi = 0; mi < 2; ++mi) {
            mma_bf16(c[mi][2 * jp],     al[mi], bh[jp][0], bh[jp][1]);
            mma_bf16(c[mi][2 * jp + 1], al[mi], bh[jp][2], bh[jp][3]);
        }
}

__global__ void __launch_bounds__(THREADS, 2)
fm_mma_kernel(const float* __restrict__ features, float* __restrict__ out)
{
    extern __shared__ __align__(16) char smem[];
    const uint32_t sb = smem_u32(smem);
    const int tid  = threadIdx.x;
    const int w    = tid >> 5;
    const int lane = tid & 31;
    const int kg   = w >> 2;            // k-group 0/1
    const int mg   = (w >> 1) & 1;      // m-group (rows 32*mg..)
    const int ng   = w & 1;             // n-group (cols 32*ng..)

    float* sqs  = (float*)(smem + SM_SQS);
    float* part = (float*)(smem + SM_PART);
    float* cp   = (float*)(smem + SM_CP);

    const size_t rowbase = (size_t)blockIdx.x * MTILE;
    const float* fblk = features + rowbase * F_DIM;

    // ---- cp.async B (pre-swizzled, no conversion): 2x 26624 B
    for (int i = tid; i < 1664; i += THREADS) {
        cp_async16(sb + SM_B_HI + i * 16, gBhi + i * 16);
        cp_async16(sb + SM_B_LO + i * 16, gBlo + i * 16);
    }
    asm volatile("cp.async.commit_group;");

    // ---- zero A K-pad (cols 200..207)
    if (tid < 128) {
        const int row = tid >> 1, c2 = 200 + 4 * (tid & 1);
        const uint32_t oa = (uint32_t)(row * SA_B + c2 * 2);
        *(uint2*)(smem + SM_A_HI + oa) = make_uint2(0, 0);
        *(uint2*)(smem + SM_A_LO + oa) = make_uint2(0, 0);
    }

    // ---- stage A: 64x200 fp32 -> bf16 hi/lo (25 pairs per thread)
    #pragma unroll 5
    for (int i = 0; i < 6400 / THREADS; ++i) {
        const int p = tid + i * THREADS;
        const int row = p / 100;
        const int c2 = 2 * (p - row * 100);
        const float2 x = *(const float2*)(fblk + row * F_DIM + c2);
        uint32_t hi, lo;
        split_bf16(x, hi, lo);
        const uint32_t o = (uint32_t)(row * SA_B + c2 * 2);
        *(uint32_t*)(smem + SM_A_HI + o) = hi;
        *(uint32_t*)(smem + SM_A_LO + o) = lo;
    }

    // ---- sq term (threads 0..127): exact fp32, features L2-hot re-read
    if (tid < 128) {
        const int row = tid >> 1, half = tid & 1;
        const float*  fr = fblk + (size_t)row * F_DIM + half * 100;
        const float4* w4 = (const float4*)(gW2s + half * 100);
        float s = 0.f;
        #pragma unroll 5
        for (int i = 0; i < 25; ++i) {
            float4 x = *(const float4*)(fr + 4 * i);
            float4 v = w4[i];
            s = fmaf(x.x * x.x, v.x, s); s = fmaf(x.y * x.y, v.y, s);
            s = fmaf(x.z * x.z, v.z, s); s = fmaf(x.w * x.w, v.w, s);
        }
        s += __shfl_xor_sync(0xffffffffu, s, 1);
        if (half == 0) sqs[row] = s;
    }

    asm volatile("cp.async.wait_group 0;" ::: "memory");
    __syncthreads();

    // ---- per-lane ldmatrix bases
    const int mrow = (lane & 7) + ((lane >> 3) & 1) * 8;  // row within 16
    const int mk   = (lane >> 4) & 1;
    const uint32_t aRow = (uint32_t)((32 * mg + mrow) * SA_B + mk * 16);
    const int bc = 4 * ng + mk;                            // B 16B-chunk
    const uint32_t bRow = (uint32_t)(mrow * 128 + ((bc ^ (mrow & 7)) << 4));
    const uint32_t aHi = sb + SM_A_HI + aRow, aLo = sb + SM_A_LO + aRow;
    const uint32_t bHi = sb + SM_B_HI + bRow, bLo = sb + SM_B_LO + bRow;

    float c[2][4][4];
    #pragma unroll
    for (int mi = 0; mi < 2; ++mi)
        #pragma unroll
        for (int j = 0; j < 4; ++j)
            #pragma unroll
            for (int q = 0; q < 4; ++q) c[mi][j][q] = 0.f;

    // ---- MMA: kg0 k=0..5, kg1 k=6..12
    if (kg == 0) {
        #pragma unroll
        for (int k = 0; k < 6; ++k) kstep(k, aHi, aLo, bHi, bLo, c);
    } else {
        #pragma unroll
        for (int k = 6; k < 13; ++k) kstep(k, aHi, aLo, bHi, bLo, c);
    }

    __syncthreads();   // all A reads done (cp aliases A_HI)

    // ---- kg1 stores partial C
    if (kg == 1) {
        const int R = 32 * mg + (lane >> 2);
        #pragma unroll
        for (int mi = 0; mi < 2; ++mi)
            #pragma unroll
            for (int j = 0; j < 4; ++j) {
                const int C = 32 * ng + 8 * j + 2 * (lane & 3);
                *(float2*)&cp[(R + 16 * mi) * CP_S + C] =
                    make_float2(c[mi][j][0], c[mi][j][1]);
                *(float2*)&cp[(R + 16 * mi + 8) * CP_S + C] =
                    make_float2(c[mi][j][2], c[mi][j][3]);
            }
    }
    __syncthreads();

    // ---- kg0: add kg1 partials, square, row-reduce
    if (kg == 0) {
        const int R = 32 * mg + (lane >> 2);
        #pragma unroll
        for (int mi = 0; mi < 2; ++mi)
            #pragma unroll
            for (int j = 0; j < 4; ++j) {
                const int C = 32 * ng + 8 * j + 2 * (lane & 3);
                float2 p0 = *(const float2*)&cp[(R + 16 * mi) * CP_S + C];
                float2 p1 = *(const float2*)&cp[(R + 16 * mi + 8) * CP_S + C];
                c[mi][j][0] += p0.x; c[mi][j][1] += p0.y;
                c[mi][j][2] += p1.x; c[mi][j][3] += p1.y;
            }
        const int g = lane >> 2, t = lane & 3;
        #pragma unroll
        for (int mi = 0; mi < 2; ++mi)
            #pragma unroll
            for (int b = 0; b < 2; ++b) {
                float s = 0.f;
                #pragma unroll
                for (int j = 0; j < 4; ++j) {
                    const float u = c[mi][j][2 * b], v = c[mi][j][2 * b + 1];
                    s = fmaf(u, u, s);
                    s = fmaf(v, v, s);
                }
                s += __shfl_xor_sync(0xffffffffu, s, 1);
                s += __shfl_xor_sync(0xffffffffu, s, 2);
                if (t == 0)
                    part[ng * 64 + 32 * mg + 16 * mi + 8 * b + g] = s;
            }
    }
    __syncthreads();

    if (tid < MTILE)
        out[rowbase + tid] = part[tid] + part[64 + tid] - sqs[tid];
}

extern "C" void kernel_launch(void* const* d_in, const int* in_sizes, int n_in,
                              void* d_out, int out_size)
{
    const float* features = (const float*)d_in[0];
    const float* W        = (const float*)d_in[1];
    if (n_in >= 2 && in_sizes[0] < in_sizes[1]) {
        features = (const float*)d_in[1];
        W        = (const float*)d_in[0];
    }
    float* out = (float*)d_out;

    cudaFuncSetAttribute(fm_mma_kernel,
                         cudaFuncAttributeMaxDynamicSharedMemorySize, SMEM_TOTAL);

    prep_kernel<<<26, 256>>>(W);

    const int B = out_size;              // 16384
    const int blocks = B / MTILE;        // 256 -> 2 CTAs/SM, single wave
    fm_mma_kernel<<<blocks, THREADS, SMEM_TOTAL>>>(features, out);
}

// round 9
// speedup vs baseline: 1.0019x; 1.0019x over previous
#include <cuda_runtime.h>
#include <cstdint>

// FM second-order term via mma.sync (HMMA) split-bf16 GEMM.
//   sum_emb = features @ W  (M=16384, K=200->208, N=64), 3 bf16 products
//   out[b]  = sum_e sum_emb[b,e]^2 - sum_f features[b,f]^2 * w2sum[f]
// R9: TRUE occupancy doubling: 2 CTAs x 512 threads per SM (8 warps/SMSP).
// MTILE=64, smem ~110KB/CTA. B pre-converted+swizzled by prep kernel
// (cp.async'd). 16 warps = kg2 x mg2 x ng4, warp tile 32m x 16n, K-half.

typedef unsigned long long ull;

constexpr int F_DIM = 200;
constexpr int E_DIM = 64;
constexpr int MTILE = 64;
constexpr int THREADS = 512;

constexpr int SA_B = 432;               // A row stride bytes (216 bf16)
constexpr int CP_S = 68;                // partial-C row stride (floats)

constexpr int SM_A_HI = 0;              // 64*432 = 27648
constexpr int SM_A_LO = 27648;
constexpr int SM_B_HI = 55296;          // 13 blocks * 2048 = 26624
constexpr int SM_B_LO = 81920;
constexpr int SM_SQS  = 108544;         // 64*4
constexpr int SM_PART = 108800;         // 4*64*4
constexpr int SMEM_TOTAL = 109824;
constexpr int SM_CP = 0;                // partial C aliases A_HI (17408<=27648)

// prep outputs: B swizzled blocks (block s = 16 k-rows * 128B; row r,
// 16B chunk c at r*128 + ((c ^ (r&7))<<4)), plus w2sum.
__device__ __align__(16) unsigned char gBhi[26624];
__device__ __align__(16) unsigned char gBlo[26624];
__device__ __align__(16) float gW2s[200];

__device__ __forceinline__ uint32_t smem_u32(const void* p) {
    return (uint32_t)__cvta_generic_to_shared(p);
}
__device__ __forceinline__ uint32_t cvt_bf16x2(float lo, float hi) {
    uint32_t r;
    asm("cvt.rn.bf16x2.f32 %0, %1, %2;" : "=r"(r) : "f"(hi), "f"(lo));
    return r;
}
__device__ __forceinline__ void split_bf16(float2 x, uint32_t& hi, uint32_t& lo) {
    hi = cvt_bf16x2(x.x, x.y);
    float h0 = __uint_as_float(hi << 16);
    float h1 = __uint_as_float(hi & 0xFFFF0000u);
    lo = cvt_bf16x2(x.x - h0, x.y - h1);
}
__device__ __forceinline__ void cp_async16(uint32_t s, const void* g) {
    asm volatile("cp.async.cg.shared.global [%0], [%1], 16;" :: "r"(s), "l"(g));
}
__device__ __forceinline__ void ldm_x4(uint32_t* r, uint32_t a) {
    asm volatile("ldmatrix.sync.aligned.m8n8.x4.shared.b16 {%0,%1,%2,%3}, [%4];"
                 : "=r"(r[0]), "=r"(r[1]), "=r"(r[2]), "=r"(r[3]) : "r"(a));
}
__device__ __forceinline__ void ldm_x4_t(uint32_t* r, uint32_t a) {
    asm volatile("ldmatrix.sync.aligned.m8n8.x4.trans.shared.b16 {%0,%1,%2,%3}, [%4];"
                 : "=r"(r[0]), "=r"(r[1]), "=r"(r[2]), "=r"(r[3]) : "r"(a));
}
__device__ __forceinline__ void mma_bf16(float* c, const uint32_t* a,
                                         uint32_t b0, uint32_t b1) {
    asm volatile(
        "mma.sync.aligned.m16n8k16.row.col.f32.bf16.bf16.f32 "
        "{%0,%1,%2,%3}, {%4,%5,%6,%7}, {%8,%9}, {%0,%1,%2,%3};"
        : "+f"(c[0]), "+f"(c[1]), "+f"(c[2]), "+f"(c[3])
        : "r"(a[0]), "r"(a[1]), "r"(a[2]), "r"(a[3]), "r"(b0), "r"(b1));
}

// ---------------- prep: convert W once, compute w2sum ----------------
__global__ void __launch_bounds__(256)
prep_kernel(const float* __restrict__ W)
{
    const int tid = threadIdx.x;
    const int k = blockIdx.x * 8 + (tid >> 5);   // B row 0..207
    const int j = tid & 31;
    uint32_t hi = 0, lo = 0;
    float2 x = make_float2(0.f, 0.f);
    if (k < F_DIM) {
        x = *(const float2*)(W + (size_t)k * E_DIM + 2 * j);
        split_bf16(x, hi, lo);
    }
    const int s = k >> 4, r = k & 15;
    const uint32_t off = (uint32_t)(s * 2048 + r * 128 +
                         (((j >> 2) ^ (r & 7)) << 4) + (j & 3) * 4);
    *(uint32_t*)(gBhi + off) = hi;
    *(uint32_t*)(gBlo + off) = lo;

    float s2 = fmaf(x.x, x.x, x.y * x.y);
    s2 += __shfl_xor_sync(0xffffffffu, s2, 1);
    s2 += __shfl_xor_sync(0xffffffffu, s2, 2);
    s2 += __shfl_xor_sync(0xffffffffu, s2, 4);
    s2 += __shfl_xor_sync(0xffffffffu, s2, 8);
    s2 += __shfl_xor_sync(0xffffffffu, s2, 16);
    if (j == 0 && k < F_DIM) gW2s[k] = s2;
}

// one k-step: 6 ldmatrix + 12 HMMA (hh*4, hl*4, lh*4 - chain-free order)
__device__ __forceinline__ void kstep(
    int k, uint32_t aHi, uint32_t aLo, uint32_t bHi, uint32_t bLo,
    float c[2][2][4])
{
    const uint32_t ka = (uint32_t)(k * 32);
    const uint32_t kb = (uint32_t)(k * 2048);
    uint32_t ah[2][4], al[2][4], bh[4], bl[4];
    ldm_x4(ah[0], aHi + ka);
    ldm_x4(ah[1], aHi + ka + 16 * SA_B);
    ldm_x4(al[0], aLo + ka);
    ldm_x4(al[1], aLo + ka + 16 * SA_B);
    ldm_x4_t(bh, bHi + kb);
    ldm_x4_t(bl, bLo + kb);
    #pragma unroll
    for (int mi = 0; mi < 2; ++mi) {
        mma_bf16(c[mi][0], ah[mi], bh[0], bh[1]);
        mma_bf16(c[mi][1], ah[mi], bh[2], bh[3]);
    }
    #pragma unroll
    for (int mi = 0; mi < 2; ++mi) {
        mma_bf16(c[mi][0], ah[mi], bl[0], bl[1]);
        mma_bf16(c[mi][1], ah[mi], bl[2], bl[3]);
    }
    #pragma unroll
    for (int mi = 0; mi < 2; ++mi) {
        mma_bf16(c[mi][0], al[mi], bh[0], bh[1]);
        mma_bf16(c[mi][1], al[mi], bh[2], bh[3]);
    }
}

__global__ void __launch_bounds__(THREADS, 2)
fm_mma_kernel(const float* __restrict__ features, float* __restrict__ out)
{
    extern __shared__ __align__(16) char smem[];
    const uint32_t sb = smem_u32(smem);
    const int tid  = threadIdx.x;
    const int w    = tid >> 5;
    const int lane = tid & 31;
    const int kg   = w >> 3;            // k-group 0/1
    const int mg   = (w >> 2) & 1;      // m-group (rows 32*mg..)
    const int ng   = w & 3;             // n-group (cols 16*ng..)

    float* sqs  = (float*)(smem + SM_SQS);
    float* part = (float*)(smem + SM_PART);
    float* cp   = (float*)(smem + SM_CP);

    const size_t rowbase = (size_t)blockIdx.x * MTILE;
    const float* fblk = features + rowbase * F_DIM;

    // ---- cp.async B (pre-swizzled, no conversion): 2x 26624 B
    for (int i = tid; i < 1664; i += THREADS) {
        cp_async16(sb + SM_B_HI + i * 16, gBhi + i * 16);
        cp_async16(sb + SM_B_LO + i * 16, gBlo + i * 16);
    }
    asm volatile("cp.async.commit_group;");

    // ---- zero A K-pad (cols 200..207)
    if (tid < 128) {
        const int row = tid >> 1, c2 = 200 + 4 * (tid & 1);
        const uint32_t oa = (uint32_t)(row * SA_B + c2 * 2);
        *(uint2*)(smem + SM_A_HI + oa) = make_uint2(0, 0);
        *(uint2*)(smem + SM_A_LO + oa) = make_uint2(0, 0);
    }

    // ---- stage A: 64x200 fp32 -> bf16 hi/lo (6400 pairs)
    #pragma unroll
    for (int i = 0; i < 13; ++i) {
        const int p = tid + i * THREADS;
        if (p < 6400) {
            const int row = p / 100;
            const int c2 = 2 * (p - row * 100);
            const float2 x = *(const float2*)(fblk + row * F_DIM + c2);
            uint32_t hi, lo;
            split_bf16(x, hi, lo);
            const uint32_t o = (uint32_t)(row * SA_B + c2 * 2);
            *(uint32_t*)(smem + SM_A_HI + o) = hi;
            *(uint32_t*)(smem + SM_A_LO + o) = lo;
        }
    }

    // ---- sq term (threads 0..127): exact fp32, features L2-hot re-read
    if (tid < 128) {
        const int row = tid >> 1, half = tid & 1;
        const float*  fr = fblk + (size_t)row * F_DIM + half * 100;
        const float4* w4 = (const float4*)(gW2s + half * 100);
        float s = 0.f;
        #pragma unroll 5
        for (int i = 0; i < 25; ++i) {
            float4 x = *(const float4*)(fr + 4 * i);
            float4 v = w4[i];
            s = fmaf(x.x * x.x, v.x, s); s = fmaf(x.y * x.y, v.y, s);
            s = fmaf(x.z * x.z, v.z, s); s = fmaf(x.w * x.w, v.w, s);
        }
        s += __shfl_xor_sync(0xffffffffu, s, 1);
        if (half == 0) sqs[row] = s;
    }

    asm volatile("cp.async.wait_group 0;" ::: "memory");
    __syncthreads();

    // ---- per-lane ldmatrix bases
    const int mrow = (lane & 7) + ((lane >> 3) & 1) * 8;  // row within 16
    const int mk   = (lane >> 4) & 1;
    const uint32_t aRow = (uint32_t)((32 * mg + mrow) * SA_B + mk * 16);
    const int bc = 2 * ng + mk;                            // B 16B-chunk
    const uint32_t bRow = (uint32_t)(mrow * 128 + ((bc ^ (mrow & 7)) << 4));
    const uint32_t aHi = sb + SM_A_HI + aRow, aLo = sb + SM_A_LO + aRow;
    const uint32_t bHi = sb + SM_B_HI + bRow, bLo = sb + SM_B_LO + bRow;

    float c[2][2][4];
    #pragma unroll
    for (int mi = 0; mi < 2; ++mi)
        #pragma unroll
        for (int j = 0; j < 2; ++j)
            #pragma unroll
            for (int q = 0; q < 4; ++q) c[mi][j][q] = 0.f;

    // ---- MMA: kg0 k=0..5, kg1 k=6..12
    if (kg == 0) {
        #pragma unroll
        for (int k = 0; k < 6; ++k) kstep(k, aHi, aLo, bHi, bLo, c);
    } else {
        #pragma unroll
        for (int k = 6; k < 13; ++k) kstep(k, aHi, aLo, bHi, bLo, c);
    }

    __syncthreads();   // all A reads done (cp aliases A_HI)

    // ---- kg1 stores partial C
    if (kg == 1) {
        const int R = 32 * mg + (lane >> 2);
        #pragma unroll
        for (int mi = 0; mi < 2; ++mi)
            #pragma unroll
            for (int j = 0; j < 2; ++j) {
                const int C = 16 * ng + 8 * j + 2 * (lane & 3);
                *(float2*)&cp[(R + 16 * mi) * CP_S + C] =
                    make_float2(c[mi][j][0], c[mi][j][1]);
                *(float2*)&cp[(R + 16 * mi + 8) * CP_S + C] =
                    make_float2(c[mi][j][2], c[mi][j][3]);
            }
    }
    __syncthreads();

    // ---- kg0: add kg1 partials, square, row-reduce over this warp's 16 cols
    if (kg == 0) {
        const int R = 32 * mg + (lane >> 2);
        #pragma unroll
        for (int mi = 0; mi < 2; ++mi)
            #pragma unroll
            for (int j = 0; j < 2; ++j) {
                const int C = 16 * ng + 8 * j + 2 * (lane & 3);
                float2 p0 = *(const float2*)&cp[(R + 16 * mi) * CP_S + C];
                float2 p1 = *(const float2*)&cp[(R + 16 * mi + 8) * CP_S + C];
                c[mi][j][0] += p0.x; c[mi][j][1] += p0.y;
                c[mi][j][2] += p1.x; c[mi][j][3] += p1.y;
            }
        const int g = lane >> 2, t = lane & 3;
        #pragma unroll
        for (int mi = 0; mi < 2; ++mi)
            #pragma unroll
            for (int b = 0; b < 2; ++b) {
                float s = 0.f;
                #pragma unroll
                for (int j = 0; j < 2; ++j) {
                    const float u = c[mi][j][2 * b], v = c[mi][j][2 * b + 1];
                    s = fmaf(u, u, s);
                    s = fmaf(v, v, s);
                }
                s += __shfl_xor_sync(0xffffffffu, s, 1);
                s += __shfl_xor_sync(0xffffffffu, s, 2);
                if (t == 0)
                    part[ng * 64 + 32 * mg + 16 * mi + 8 * b + g] = s;
            }
    }
    __syncthreads();

    if (tid < MTILE)
        out[rowbase + tid] = part[tid] + part[64 + tid] + part[128 + tid] +
                             part[192 + tid] - sqs[tid];
}

extern "C" void kernel_launch(void* const* d_in, const int* in_sizes, int n_in,
                              void* d_out, int out_size)
{
    const float* features = (const float*)d_in[0];
    const float* W        = (const float*)d_in[1];
    if (n_in >= 2 && in_sizes[0] < in_sizes[1]) {
        features = (const float*)d_in[1];
        W        = (const float*)d_in[0];
    }
    float* out = (float*)d_out;

    cudaFuncSetAttribute(fm_mma_kernel,
                         cudaFuncAttributeMaxDynamicSharedMemorySize, SMEM_TOTAL);

    prep_kernel<<<26, 256>>>(W);

    const int B = out_size;              // 16384
    const int blocks = B / MTILE;        // 256 -> 2 CTAs/SM, single wave
    fm_mma_kernel<<<blocks, THREADS, SMEM_TOTAL>>>(features, out);
}